// round 4
// baseline (speedup 1.0000x reference)
#include <cuda_runtime.h>
#include <cuda_bf16.h>
#include <math.h>
#include <stdint.h>

#define BB 2
#define SS 2048
#define DM 1024
#define NH 16
#define DKK 64
#define DFF 4096
#define MT (BB*SS)   // 4096 tokens

#define NELEM_1M (DM*DM)          // 1048576
#define WQO 0
#define WKO (1*NELEM_1M)
#define WVO (2*NELEM_1M)
#define WOO (3*NELEM_1M)
#define W1O (4*NELEM_1M)
#define W3O (8*NELEM_1M)
#define W2O (12*NELEM_1M)
#define WTOT (16*NELEM_1M)

// ---------------- scratch (__device__ globals; no allocations) ----------------
__device__ float g_lin[(size_t)3*MT*DM];
__device__ float g_q  [(size_t)MT*DM];
__device__ float g_k  [(size_t)MT*DM];
__device__ float g_v  [(size_t)MT*DM];
__device__ float g_x1 [(size_t)MT*DM];
__device__ float g_a  [(size_t)MT*DFF];
__device__ float g_g  [(size_t)MT*DFF];
// bf16 split operand buffers
__device__ __nv_bfloat16 g_wh [(size_t)WTOT];
__device__ __nv_bfloat16 g_wl [(size_t)WTOT];
__device__ __nv_bfloat16 g_xnh[(size_t)MT*DM];
__device__ __nv_bfloat16 g_xnl[(size_t)MT*DM];
__device__ __nv_bfloat16 g_ath[(size_t)MT*DM];
__device__ __nv_bfloat16 g_atl[(size_t)MT*DM];
__device__ __nv_bfloat16 g_hh [(size_t)MT*DFF];
__device__ __nv_bfloat16 g_hl [(size_t)MT*DFF];

// ================= helpers =================
__device__ __forceinline__ uint32_t smem_u32(const void* p) {
    uint32_t a;
    asm("{ .reg .u64 t; cvta.to.shared.u64 t, %1; cvt.u32.u64 %0, t; }" : "=r"(a) : "l"(p));
    return a;
}
__device__ __forceinline__ void ldm_x4(uint32_t* r, uint32_t addr) {
    asm volatile("ldmatrix.sync.aligned.m8n8.x4.shared.b16 {%0,%1,%2,%3}, [%4];"
        : "=r"(r[0]),"=r"(r[1]),"=r"(r[2]),"=r"(r[3]) : "r"(addr));
}
__device__ __forceinline__ void mma_bf16(float* d,
        uint32_t a0, uint32_t a1, uint32_t a2, uint32_t a3,
        uint32_t b0, uint32_t b1) {
    asm volatile("mma.sync.aligned.m16n8k16.row.col.f32.bf16.bf16.f32 "
        "{%0,%1,%2,%3}, {%4,%5,%6,%7}, {%8,%9}, {%0,%1,%2,%3};"
        : "+f"(d[0]),"+f"(d[1]),"+f"(d[2]),"+f"(d[3])
        : "r"(a0),"r"(a1),"r"(a2),"r"(a3),"r"(b0),"r"(b1));
}
__device__ __forceinline__ void cp16(uint32_t dst, const void* src) {
    asm volatile("cp.async.cg.shared.global [%0], [%1], 16;" :: "r"(dst), "l"(src));
}
#define CP_COMMIT() asm volatile("cp.async.commit_group;" ::: "memory")
#define CP_WAIT3()  asm volatile("cp.async.wait_group 3;" ::: "memory")

// split float4 -> 4 bf16 hi (uint2) + 4 bf16 lo (uint2)
__device__ __forceinline__ void split4(float4 v, uint2& h, uint2& l) {
    __nv_bfloat162 h0 = __floats2bfloat162_rn(v.x, v.y);
    __nv_bfloat162 h1 = __floats2bfloat162_rn(v.z, v.w);
    uint32_t u0 = *reinterpret_cast<uint32_t*>(&h0);
    uint32_t u1 = *reinterpret_cast<uint32_t*>(&h1);
    float rx = v.x - __uint_as_float(u0 << 16);
    float ry = v.y - __uint_as_float(u0 & 0xffff0000u);
    float rz = v.z - __uint_as_float(u1 << 16);
    float rw = v.w - __uint_as_float(u1 & 0xffff0000u);
    __nv_bfloat162 l0 = __floats2bfloat162_rn(rx, ry);
    __nv_bfloat162 l1 = __floats2bfloat162_rn(rz, rw);
    h = make_uint2(u0, u1);
    l = make_uint2(*reinterpret_cast<uint32_t*>(&l0), *reinterpret_cast<uint32_t*>(&l1));
}

// ---------------- weight split: fp32 -> bf16 hi/lo ----------------
__global__ void split_w(const float4* __restrict__ src, uint2* __restrict__ hi,
                        uint2* __restrict__ lo, int n4) {
    int i = blockIdx.x * blockDim.x + threadIdx.x;
    if (i >= n4) return;
    uint2 h, l;
    split4(src[i], h, l);
    hi[i] = h; lo[i] = l;
}

// ================= split-bf16 tensor-core GEMM (mma.sync + cp.async) =================
// C[M,N] = (Ah+Al)[M,K] * (Bh+Bl)[N,K]^T (+R), dropping Al*Bl. fp32 out.
// 128x128 CTA tile, BK=32, 4-stage cp.async pipeline, smem row stride 80B.
#define BK 32
#define ROWB 80
#define MATB (128*ROWB)            // 10240
#define STAGEB (4*MATB)            // 40960: Ah, Al, Bh, Bl
#define NSTG 4
#define GEMM_SMEM (NSTG*STAGEB)    // 163840

__global__ void __launch_bounds__(256, 1) gemm_mma(
    const __nv_bfloat16* __restrict__ Ah, const __nv_bfloat16* __restrict__ Al,
    const __nv_bfloat16* __restrict__ Bh, const __nv_bfloat16* __restrict__ Bl,
    const float* __restrict__ R, float* __restrict__ C,
    int M, int N, int K)
{
    extern __shared__ char smem[];
    const uint32_t sb = smem_u32(smem);
    const int tid = threadIdx.x;
    const int wid = tid >> 5, lane = tid & 31;
    const int bm = blockIdx.y * 128, bn = blockIdx.x * 128;
    const int wm = (wid & 1) * 64, wn = (wid >> 1) * 32;

    const int a_r16 = lane & 15, a_kh = lane >> 4;
    const int b_row = (lane & 7) + ((lane & 16) ? 8 : 0);
    const int b_kh = (lane >> 3) & 1;

    // issue one stage's cp.async loads: 8 x 16B per thread (2 per matrix)
    auto issue = [&](int c, int buf) {
        const uint32_t stg = sb + (uint32_t)buf * STAGEB;
        #pragma unroll
        for (int i = 0; i < 8; i++) {
            const int mat = i >> 1;                        // compile-time after unroll
            const int c16 = (i & 1) * 256 + tid;           // 0..511
            const int row = c16 >> 2, j = c16 & 3;
            const __nv_bfloat16* bp = (mat == 0) ? Ah : (mat == 1) ? Al
                                    : (mat == 2) ? Bh : Bl;
            const int gr = ((mat < 2) ? bm : bn) + row;
            cp16(stg + (uint32_t)(mat * MATB + row * ROWB + j * 16),
                 bp + (size_t)gr * K + c * BK + j * 8);
        }
        CP_COMMIT();
    };

    float acc[4][4][4];
    #pragma unroll
    for (int mi = 0; mi < 4; mi++)
        #pragma unroll
        for (int ni = 0; ni < 4; ni++)
            #pragma unroll
            for (int r = 0; r < 4; r++) acc[mi][ni][r] = 0.f;

    const int NC = K >> 5;
    issue(0, 0); issue(1, 1); issue(2, 2);

    for (int c = 0; c < NC; c++) {
        if (c + 3 < NC) issue(c + 3, (c + 3) & 3);
        else CP_COMMIT();
        CP_WAIT3();
        __syncthreads();

        const uint32_t base = sb + (uint32_t)(c & 3) * STAGEB;
        #pragma unroll
        for (int kk = 0; kk < 2; kk++) {
            uint32_t ah[4][4], al[4][4], bh[2][4], bl[2][4];
            #pragma unroll
            for (int mi = 0; mi < 4; mi++) {
                uint32_t ad = base + (uint32_t)((wm + mi*16 + a_r16) * ROWB + kk*32 + a_kh*16);
                ldm_x4(ah[mi], ad);
                ldm_x4(al[mi], ad + MATB);
            }
            #pragma unroll
            for (int p = 0; p < 2; p++) {
                uint32_t bd = base + (uint32_t)(2*MATB
                            + (wn + p*16 + b_row) * ROWB + kk*32 + b_kh*16);
                ldm_x4(bh[p], bd);
                ldm_x4(bl[p], bd + MATB);
            }
            #pragma unroll
            for (int mi = 0; mi < 4; mi++) {
                #pragma unroll
                for (int ni = 0; ni < 4; ni++) {
                    const int p = ni >> 1, s = (ni & 1) * 2;
                    mma_bf16(acc[mi][ni], ah[mi][0], ah[mi][1], ah[mi][2], ah[mi][3],
                             bh[p][s], bh[p][s+1]);
                    mma_bf16(acc[mi][ni], ah[mi][0], ah[mi][1], ah[mi][2], ah[mi][3],
                             bl[p][s], bl[p][s+1]);
                    mma_bf16(acc[mi][ni], al[mi][0], al[mi][1], al[mi][2], al[mi][3],
                             bh[p][s], bh[p][s+1]);
                }
            }
        }
        __syncthreads();
    }

    // ---- epilogue ----
    const int g = lane >> 2, tg = lane & 3;
    #pragma unroll
    for (int mi = 0; mi < 4; mi++) {
        #pragma unroll
        for (int ni = 0; ni < 4; ni++) {
            int r0 = bm + wm + mi*16 + g;
            int c0 = bn + wn + ni*8 + tg*2;
            float* d = acc[mi][ni];
            if (R) {
                float2 rv0 = *(const float2*)(R + (size_t)r0 * N + c0);
                float2 rv1 = *(const float2*)(R + (size_t)(r0+8) * N + c0);
                *(float2*)(C + (size_t)r0 * N + c0)     = make_float2(d[0]+rv0.x, d[1]+rv0.y);
                *(float2*)(C + (size_t)(r0+8) * N + c0) = make_float2(d[2]+rv1.x, d[3]+rv1.y);
            } else {
                *(float2*)(C + (size_t)r0 * N + c0)     = make_float2(d[0], d[1]);
                *(float2*)(C + (size_t)(r0+8) * N + c0) = make_float2(d[2], d[3]);
            }
        }
    }
}

// ---------------- rmsnorm: one row per block, emits bf16 hi/lo ----------------
__global__ void rmsnorm_k(const float* __restrict__ x, const float* __restrict__ w,
                          uint2* __restrict__ oh, uint2* __restrict__ ol) {
    int row = blockIdx.x;
    int t = threadIdx.x;
    float4 xv = ((const float4*)(x + (size_t)row*DM))[t];
    float s = xv.x*xv.x + xv.y*xv.y + xv.z*xv.z + xv.w*xv.w;
    #pragma unroll
    for (int o = 16; o > 0; o >>= 1) s += __shfl_xor_sync(0xffffffffu, s, o);
    __shared__ float ws[8];
    __shared__ float s_inv;
    if ((t & 31) == 0) ws[t >> 5] = s;
    __syncthreads();
    if (t == 0) {
        float tot = 0.f;
        #pragma unroll
        for (int i = 0; i < 8; i++) tot += ws[i];
        s_inv = rsqrtf(tot / (float)DM + 1e-5f);
    }
    __syncthreads();
    float inv = s_inv;
    float4 wv = ((const float4*)w)[t];
    float4 ov;
    ov.x = xv.x*inv*wv.x; ov.y = xv.y*inv*wv.y;
    ov.z = xv.z*inv*wv.z; ov.w = xv.w*inv*wv.w;
    uint2 h, l;
    split4(ov, h, l);
    oh[(size_t)row*256 + t] = h;
    ol[(size_t)row*256 + t] = l;
}

// ---------------- RoPE + head permute ----------------
__global__ void rope_perm_k(const float* __restrict__ lin, const int* __restrict__ pos,
                            float* __restrict__ q, float* __restrict__ k,
                            float* __restrict__ v) {
    int idx = blockIdx.x * blockDim.x + threadIdx.x;
    if (idx >= MT * NH * (DKK/2)) return;
    int i  = idx & 31;
    int hh = (idx >> 5) & (NH-1);
    int t  = idx >> 9;
    int b  = t >> 11;
    int s  = t & (SS - 1);
    size_t src = (size_t)t * DM + hh * DKK + 2*i;
    size_t dst = ((size_t)(b*NH + hh) * SS + s) * DKK + 2*i;
    double ex = -((double)(2*i) / 64.0) * 9.210340371976184;
    float invf = (float)exp(ex);
    float ang = (float)pos[t] * invf;
    float sn, cs;
    sincosf(ang, &sn, &cs);
    float qe = lin[src], qo = lin[src+1];
    q[dst]   = qe*cs - qo*sn;
    q[dst+1] = qe*sn + qo*cs;
    const float* link = lin + (size_t)MT*DM;
    float ke = link[src], ko = link[src+1];
    k[dst]   = ke*cs - ko*sn;
    k[dst+1] = ke*sn + ko*cs;
    const float* linv = lin + (size_t)2*MT*DM;
    v[dst]   = linv[src];
    v[dst+1] = linv[src+1];
}

// ---------------- Flash attention, causal, 64x64 tiles, fp32, bf16-split output ----------------
#define ATT_SMEM (4*64*68*4)
__global__ void __launch_bounds__(256) attn_k(
    const float* __restrict__ Q, const float* __restrict__ Kg,
    const float* __restrict__ Vg, uint2* __restrict__ Oh, uint2* __restrict__ Ol)
{
    extern __shared__ float sm[];
    float* Qt = sm;
    float* Kt = sm + 64*68;
    float* Vs = sm + 2*64*68;
    float* Ps = sm + 3*64*68;
    const int qt = blockIdx.x, h = blockIdx.y, b = blockIdx.z;
    const int tid = threadIdx.x;
    const int tr = tid >> 4;
    const int tc = tid & 15;
    const int q0 = qt * 64;
    const float* Qh = Q  + (size_t)(b*NH + h) * SS * DKK;
    const float* Kh = Kg + (size_t)(b*NH + h) * SS * DKK;
    const float* Vh = Vg + (size_t)(b*NH + h) * SS * DKK;
    const int lr = tid >> 4;
    const int lc = (tid & 15) * 4;

    #pragma unroll
    for (int i = 0; i < 4; i++) {
        int rr = lr + i*16;
        float4 t4 = *(const float4*)(Qh + (size_t)(q0 + rr)*DKK + lc);
        Qt[(lc+0)*68 + rr] = t4.x; Qt[(lc+1)*68 + rr] = t4.y;
        Qt[(lc+2)*68 + rr] = t4.z; Qt[(lc+3)*68 + rr] = t4.w;
    }

    float o[4][4];
    #pragma unroll
    for (int i = 0; i < 4; i++)
        #pragma unroll
        for (int c = 0; c < 4; c++) o[i][c] = 0.f;
    float m[4], l[4];
    #pragma unroll
    for (int i = 0; i < 4; i++) { m[i] = -1e30f; l[i] = 0.f; }

    for (int kt = 0; kt <= qt; kt++) {
        int k0 = kt * 64;
        __syncthreads();
        #pragma unroll
        for (int i = 0; i < 4; i++) {
            int rr = lr + i*16;
            float4 t4 = *(const float4*)(Kh + (size_t)(k0 + rr)*DKK + lc);
            Kt[(lc+0)*68 + rr] = t4.x; Kt[(lc+1)*68 + rr] = t4.y;
            Kt[(lc+2)*68 + rr] = t4.z; Kt[(lc+3)*68 + rr] = t4.w;
            float4 v4 = *(const float4*)(Vh + (size_t)(k0 + rr)*DKK + lc);
            *(float4*)&Vs[rr*68 + lc] = v4;
        }
        __syncthreads();

        float sv[4][4];
        #pragma unroll
        for (int i = 0; i < 4; i++)
            #pragma unroll
            for (int j = 0; j < 4; j++) sv[i][j] = 0.f;
        #pragma unroll 8
        for (int d = 0; d < DKK; d++) {
            float qa[4], kb[4];
            *(float4*)qa = *(const float4*)&Qt[d*68 + tr*4];
            *(float4*)kb = *(const float4*)&Kt[d*68 + tc*4];
            #pragma unroll
            for (int i = 0; i < 4; i++)
                #pragma unroll
                for (int j = 0; j < 4; j++)
                    sv[i][j] = fmaf(qa[i], kb[j], sv[i][j]);
        }

        #pragma unroll
        for (int i = 0; i < 4; i++) {
            int grow = q0 + tr*4 + i;
            #pragma unroll
            for (int j = 0; j < 4; j++) {
                int gcol = k0 + tc*4 + j;
                sv[i][j] = (gcol <= grow) ? sv[i][j] * 0.125f : -1e30f;
            }
        }

        #pragma unroll
        for (int i = 0; i < 4; i++) {
            float rm = fmaxf(fmaxf(sv[i][0], sv[i][1]), fmaxf(sv[i][2], sv[i][3]));
            #pragma unroll
            for (int off = 1; off < 16; off <<= 1)
                rm = fmaxf(rm, __shfl_xor_sync(0xffffffffu, rm, off));
            float mn = fmaxf(m[i], rm);
            float alpha = __expf(m[i] - mn);
            float rs = 0.f;
            #pragma unroll
            for (int j = 0; j < 4; j++) {
                sv[i][j] = __expf(sv[i][j] - mn);
                rs += sv[i][j];
            }
            #pragma unroll
            for (int off = 1; off < 16; off <<= 1)
                rs += __shfl_xor_sync(0xffffffffu, rs, off);
            l[i] = l[i] * alpha + rs;
            m[i] = mn;
            #pragma unroll
            for (int c = 0; c < 4; c++) o[i][c] *= alpha;
            *(float4*)&Ps[(tr*4 + i)*68 + tc*4] =
                make_float4(sv[i][0], sv[i][1], sv[i][2], sv[i][3]);
        }
        __syncthreads();

        #pragma unroll 4
        for (int j = 0; j < 64; j++) {
            float vb[4];
            *(float4*)vb = *(const float4*)&Vs[j*68 + tc*4];
            #pragma unroll
            for (int i = 0; i < 4; i++) {
                float p = Ps[(tr*4 + i)*68 + j];
                #pragma unroll
                for (int c = 0; c < 4; c++)
                    o[i][c] = fmaf(p, vb[c], o[i][c]);
            }
        }
    }

    #pragma unroll
    for (int i = 0; i < 4; i++) {
        float inv = 1.f / l[i];
        int row = q0 + tr*4 + i;
        float4 ov = make_float4(o[i][0]*inv, o[i][1]*inv, o[i][2]*inv, o[i][3]*inv);
        uint2 hh2, ll2;
        split4(ov, hh2, ll2);
        size_t idx4 = (((size_t)(b*SS + row)*DM) + h*DKK + tc*4) >> 2;
        Oh[idx4] = hh2;
        Ol[idx4] = ll2;
    }
}

// ---------------- silu(a) * g -> bf16 hi/lo ----------------
__global__ void silu_mul_k(const float4* __restrict__ a, const float4* __restrict__ g,
                           uint2* __restrict__ hh, uint2* __restrict__ hl, int n4) {
    int i = blockIdx.x * blockDim.x + threadIdx.x;
    if (i >= n4) return;
    float4 av = a[i], gv = g[i], r;
    r.x = (av.x / (1.f + __expf(-av.x))) * gv.x;
    r.y = (av.y / (1.f + __expf(-av.y))) * gv.y;
    r.z = (av.z / (1.f + __expf(-av.z))) * gv.z;
    r.w = (av.w / (1.f + __expf(-av.w))) * gv.w;
    uint2 h, l;
    split4(r, h, l);
    hh[i] = h; hl[i] = l;
}

// ---------------- launcher ----------------
extern "C" void kernel_launch(void* const* d_in, const int* in_sizes, int n_in,
                              void* d_out, int out_size) {
    const float* x   = (const float*)d_in[0];
    const int*   pos = (const int*)  d_in[1];
    const float* n1w = (const float*)d_in[2];
    const float* n2w = (const float*)d_in[3];
    const float* wq  = (const float*)d_in[4];
    const float* wk  = (const float*)d_in[5];
    const float* wv  = (const float*)d_in[6];
    const float* wo  = (const float*)d_in[7];
    const float* w1  = (const float*)d_in[8];
    const float* w2  = (const float*)d_in[9];
    const float* w3  = (const float*)d_in[10];
    float* out = (float*)d_out;

    float *lin, *q, *k, *v, *x1, *a, *g;
    __nv_bfloat16 *wh, *wl, *xnh, *xnl, *ath, *atl, *hh, *hl;
    cudaGetSymbolAddress((void**)&lin, g_lin);
    cudaGetSymbolAddress((void**)&q,   g_q);
    cudaGetSymbolAddress((void**)&k,   g_k);
    cudaGetSymbolAddress((void**)&v,   g_v);
    cudaGetSymbolAddress((void**)&x1,  g_x1);
    cudaGetSymbolAddress((void**)&a,   g_a);
    cudaGetSymbolAddress((void**)&g,   g_g);
    cudaGetSymbolAddress((void**)&wh,  g_wh);
    cudaGetSymbolAddress((void**)&wl,  g_wl);
    cudaGetSymbolAddress((void**)&xnh, g_xnh);
    cudaGetSymbolAddress((void**)&xnl, g_xnl);
    cudaGetSymbolAddress((void**)&ath, g_ath);
    cudaGetSymbolAddress((void**)&atl, g_atl);
    cudaGetSymbolAddress((void**)&hh,  g_hh);
    cudaGetSymbolAddress((void**)&hl,  g_hl);

    cudaFuncSetAttribute(attn_k, cudaFuncAttributeMaxDynamicSharedMemorySize, ATT_SMEM);
    cudaFuncSetAttribute(gemm_mma, cudaFuncAttributeMaxDynamicSharedMemorySize, GEMM_SMEM);

    // 0) split weights to bf16 hi/lo
    split_w<<<(NELEM_1M/4)/256, 256>>>((const float4*)wq, (uint2*)(wh+WQO), (uint2*)(wl+WQO), NELEM_1M/4);
    split_w<<<(NELEM_1M/4)/256, 256>>>((const float4*)wk, (uint2*)(wh+WKO), (uint2*)(wl+WKO), NELEM_1M/4);
    split_w<<<(NELEM_1M/4)/256, 256>>>((const float4*)wv, (uint2*)(wh+WVO), (uint2*)(wl+WVO), NELEM_1M/4);
    split_w<<<(NELEM_1M/4)/256, 256>>>((const float4*)wo, (uint2*)(wh+WOO), (uint2*)(wl+WOO), NELEM_1M/4);
    split_w<<<(4*NELEM_1M/4)/256, 256>>>((const float4*)w1, (uint2*)(wh+W1O), (uint2*)(wl+W1O), NELEM_1M);
    split_w<<<(4*NELEM_1M/4)/256, 256>>>((const float4*)w3, (uint2*)(wh+W3O), (uint2*)(wl+W3O), NELEM_1M);
    split_w<<<(4*NELEM_1M/4)/256, 256>>>((const float4*)w2, (uint2*)(wh+W2O), (uint2*)(wl+W2O), NELEM_1M);

    // 1) rmsnorm 1 -> bf16 hi/lo
    rmsnorm_k<<<MT, 256>>>(x, n1w, (uint2*)xnh, (uint2*)xnl);
    // 2) QKV projections
    gemm_mma<<<dim3(DM/128, MT/128), 256, GEMM_SMEM>>>(xnh, xnl, wh+WQO, wl+WQO, nullptr, lin,                   MT, DM, DM);
    gemm_mma<<<dim3(DM/128, MT/128), 256, GEMM_SMEM>>>(xnh, xnl, wh+WKO, wl+WKO, nullptr, lin + (size_t)MT*DM,   MT, DM, DM);
    gemm_mma<<<dim3(DM/128, MT/128), 256, GEMM_SMEM>>>(xnh, xnl, wh+WVO, wl+WVO, nullptr, lin + (size_t)2*MT*DM, MT, DM, DM);
    // 3) rope + permute
    rope_perm_k<<<(MT*NH*(DKK/2))/256, 256>>>(lin, pos, q, k, v);
    // 4) attention -> bf16 hi/lo
    attn_k<<<dim3(SS/64, NH, BB), 256, ATT_SMEM>>>(q, k, v, (uint2*)ath, (uint2*)atl);
    // 5) output projection + residual
    gemm_mma<<<dim3(DM/128, MT/128), 256, GEMM_SMEM>>>(ath, atl, wh+WOO, wl+WOO, x, x1, MT, DM, DM);
    // 6) rmsnorm 2 -> bf16 hi/lo
    rmsnorm_k<<<MT, 256>>>(x1, n2w, (uint2*)xnh, (uint2*)xnl);
    // 7) FFN up
    gemm_mma<<<dim3(DFF/128, MT/128), 256, GEMM_SMEM>>>(xnh, xnl, wh+W1O, wl+W1O, nullptr, a, MT, DFF, DM);
    gemm_mma<<<dim3(DFF/128, MT/128), 256, GEMM_SMEM>>>(xnh, xnl, wh+W3O, wl+W3O, nullptr, g, MT, DFF, DM);
    // 8) h = silu(a)*g -> bf16 hi/lo
    silu_mul_k<<<(MT*DFF/4 + 255)/256, 256>>>((const float4*)a, (const float4*)g,
                                              (uint2*)hh, (uint2*)hl, MT*DFF/4);
    // 9) down projection + residual -> output
    gemm_mma<<<dim3(DM/128, MT/128), 256, GEMM_SMEM>>>(hh, hl, wh+W2O, wl+W2O, x1, out, MT, DM, DFF);
}

// round 5
// speedup vs baseline: 1.1169x; 1.1169x over previous
#include <cuda_runtime.h>
#include <cuda_bf16.h>
#include <math.h>
#include <stdint.h>

#define BB 2
#define SS 2048
#define DM 1024
#define NH 16
#define DKK 64
#define DFF 4096
#define MT (BB*SS)   // 4096 tokens

// ---------------- scratch (__device__ globals; no allocations) ----------------
__device__ float g_xn [(size_t)MT*DM];
__device__ float g_lin[(size_t)3*MT*DM];
__device__ float g_q  [(size_t)MT*DM];
__device__ float g_k  [(size_t)MT*DM];
__device__ float g_v  [(size_t)MT*DM];
__device__ float g_att[(size_t)MT*DM];
__device__ float g_x1 [(size_t)MT*DM];
__device__ float g_a  [(size_t)MT*DFF];
__device__ float g_g  [(size_t)MT*DFF];

// ================= helpers =================
__device__ __forceinline__ uint32_t smem_u32(const void* p) {
    uint32_t a;
    asm("{ .reg .u64 t; cvta.to.shared.u64 t, %1; cvt.u32.u64 %0, t; }" : "=r"(a) : "l"(p));
    return a;
}
__device__ __forceinline__ void ldm_x4(uint32_t* r, uint32_t addr) {
    asm volatile("ldmatrix.sync.aligned.m8n8.x4.shared.b16 {%0,%1,%2,%3}, [%4];"
        : "=r"(r[0]),"=r"(r[1]),"=r"(r[2]),"=r"(r[3]) : "r"(addr));
}
__device__ __forceinline__ void mma_bf16(float* d,
        uint32_t a0, uint32_t a1, uint32_t a2, uint32_t a3,
        uint32_t b0, uint32_t b1) {
    asm volatile("mma.sync.aligned.m16n8k16.row.col.f32.bf16.bf16.f32 "
        "{%0,%1,%2,%3}, {%4,%5,%6,%7}, {%8,%9}, {%0,%1,%2,%3};"
        : "+f"(d[0]),"+f"(d[1]),"+f"(d[2]),"+f"(d[3])
        : "r"(a0),"r"(a1),"r"(a2),"r"(a3),"r"(b0),"r"(b1));
}

// split fp32x4 -> 4 bf16 hi (8B) + 4 bf16 lo (8B), store to smem
__device__ __forceinline__ void cvt_split8(uint32_t hi_addr, uint32_t lo_addr, float4 v) {
    __nv_bfloat162 h0 = __floats2bfloat162_rn(v.x, v.y);
    __nv_bfloat162 h1 = __floats2bfloat162_rn(v.z, v.w);
    uint32_t u0 = *reinterpret_cast<uint32_t*>(&h0);
    uint32_t u1 = *reinterpret_cast<uint32_t*>(&h1);
    float rx = v.x - __uint_as_float(u0 << 16);
    float ry = v.y - __uint_as_float(u0 & 0xffff0000u);
    float rz = v.z - __uint_as_float(u1 << 16);
    float rw = v.w - __uint_as_float(u1 & 0xffff0000u);
    __nv_bfloat162 l0 = __floats2bfloat162_rn(rx, ry);
    __nv_bfloat162 l1 = __floats2bfloat162_rn(rz, rw);
    uint32_t w0 = *reinterpret_cast<uint32_t*>(&l0);
    uint32_t w1 = *reinterpret_cast<uint32_t*>(&l1);
    asm volatile("st.shared.v2.b32 [%0], {%1, %2};" :: "r"(hi_addr), "r"(u0), "r"(u1));
    asm volatile("st.shared.v2.b32 [%0], {%1, %2};" :: "r"(lo_addr), "r"(w0), "r"(w1));
}

// ================= split-bf16 tensor-core GEMM (mma.sync, 512 threads) =================
// C[M,N] = A[M,K] * B[N,K]^T (+ optional residual R). fp32 in/out.
// 128x128 CTA tile, BK=32, double-buffered smem, 16 warps (warp tile 32x32).
#define BK 32
#define ROWB 80                    // bytes per row in smem (64B data + 16B pad)
#define MATB (128*ROWB)            // 10240 B per matrix tile
#define STAGEB (4*MATB)            // A_hi, A_lo, B_hi, B_lo
#define GEMM_SMEM (2*STAGEB)       // 81920 B

__global__ void __launch_bounds__(512, 1) gemm_mma(
    const float* __restrict__ A, const float* __restrict__ B,
    const float* __restrict__ R, float* __restrict__ C,
    int M, int N, int K)
{
    extern __shared__ char smem[];
    const uint32_t sb = smem_u32(smem);
    const int tid = threadIdx.x;
    const int wid = tid >> 5, lane = tid & 31;
    const int bm = blockIdx.y * 128, bn = blockIdx.x * 128;
    const int wm = (wid & 3) * 32, wn = (wid >> 2) * 32;   // 4x4 warp grid, 32x32 tiles

    const int a_r16 = lane & 15, a_kh = lane >> 4;
    const int b_row = (lane & 7) + ((lane & 16) ? 8 : 0);
    const int b_kh = (lane >> 3) & 1;

    float acc[2][4][4];
    #pragma unroll
    for (int mi = 0; mi < 2; mi++)
        #pragma unroll
        for (int ni = 0; ni < 4; ni++)
            #pragma unroll
            for (int r = 0; r < 4; r++) acc[mi][ni][r] = 0.f;

    const int NC = K >> 5;  // K/32

    // ---- prologue: load + convert stage 0 ----
    {
        const float* At = A + (size_t)bm * K;
        const float* Bt = B + (size_t)bn * K;
        #pragma unroll
        for (int i = 0; i < 2; i++) {
            int idx = tid + i * 512;
            int row = idx >> 3, f4 = idx & 7;
            uint32_t off = (uint32_t)(row * ROWB + f4 * 8);
            float4 av = *(const float4*)(At + (size_t)row * K + f4 * 4);
            cvt_split8(sb + off, sb + MATB + off, av);
            float4 bv = *(const float4*)(Bt + (size_t)row * K + f4 * 4);
            cvt_split8(sb + 2*MATB + off, sb + 3*MATB + off, bv);
        }
    }
    __syncthreads();

    for (int c = 0; c < NC; c++) {
        const int stg = c & 1;
        const uint32_t base = sb + stg * STAGEB;

        // ---- issue next-stage global loads early (into registers) ----
        float4 aw[2], bw[2];
        if (c + 1 < NC) {
            const float* At = A + (size_t)bm * K + (c + 1) * BK;
            const float* Bt = B + (size_t)bn * K + (c + 1) * BK;
            #pragma unroll
            for (int i = 0; i < 2; i++) {
                int idx = tid + i * 512;
                int row = idx >> 3, f4 = idx & 7;
                aw[i] = *(const float4*)(At + (size_t)row * K + f4 * 4);
                bw[i] = *(const float4*)(Bt + (size_t)row * K + f4 * 4);
            }
        }

        // ---- compute current stage ----
        #pragma unroll
        for (int kk = 0; kk < 2; kk++) {
            uint32_t ah[2][4], al[2][4], bh[2][4], bl[2][4];
            #pragma unroll
            for (int mi = 0; mi < 2; mi++) {
                uint32_t ad = base + (uint32_t)((wm + mi*16 + a_r16) * ROWB + kk*32 + a_kh*16);
                ldm_x4(ah[mi], ad);
                ldm_x4(al[mi], ad + MATB);
            }
            #pragma unroll
            for (int p = 0; p < 2; p++) {
                uint32_t bd = base + (uint32_t)(2*MATB
                            + (wn + p*16 + b_row) * ROWB + kk*32 + b_kh*16);
                ldm_x4(bh[p], bd);
                ldm_x4(bl[p], bd + MATB);
            }
            #pragma unroll
            for (int mi = 0; mi < 2; mi++) {
                #pragma unroll
                for (int ni = 0; ni < 4; ni++) {
                    const int p = ni >> 1, s = (ni & 1) * 2;
                    mma_bf16(acc[mi][ni], ah[mi][0], ah[mi][1], ah[mi][2], ah[mi][3],
                             bh[p][s], bh[p][s+1]);
                    mma_bf16(acc[mi][ni], ah[mi][0], ah[mi][1], ah[mi][2], ah[mi][3],
                             bl[p][s], bl[p][s+1]);
                    mma_bf16(acc[mi][ni], al[mi][0], al[mi][1], al[mi][2], al[mi][3],
                             bh[p][s], bh[p][s+1]);
                }
            }
        }

        // ---- convert + store next stage ----
        if (c + 1 < NC) {
            const uint32_t nb = sb + (stg ^ 1) * STAGEB;
            #pragma unroll
            for (int i = 0; i < 2; i++) {
                int idx = tid + i * 512;
                int row = idx >> 3, f4 = idx & 7;
                uint32_t off = (uint32_t)(row * ROWB + f4 * 8);
                cvt_split8(nb + off, nb + MATB + off, aw[i]);
                cvt_split8(nb + 2*MATB + off, nb + 3*MATB + off, bw[i]);
            }
        }
        __syncthreads();
    }

    // ---- epilogue ----
    const int g = lane >> 2, tg = lane & 3;
    #pragma unroll
    for (int mi = 0; mi < 2; mi++) {
        #pragma unroll
        for (int ni = 0; ni < 4; ni++) {
            int r0 = bm + wm + mi*16 + g;
            int c0 = bn + wn + ni*8 + tg*2;
            float* d = acc[mi][ni];
            if (R) {
                float2 rv0 = *(const float2*)(R + (size_t)r0 * N + c0);
                float2 rv1 = *(const float2*)(R + (size_t)(r0+8) * N + c0);
                *(float2*)(C + (size_t)r0 * N + c0)     = make_float2(d[0]+rv0.x, d[1]+rv0.y);
                *(float2*)(C + (size_t)(r0+8) * N + c0) = make_float2(d[2]+rv1.x, d[3]+rv1.y);
            } else {
                *(float2*)(C + (size_t)r0 * N + c0)     = make_float2(d[0], d[1]);
                *(float2*)(C + (size_t)(r0+8) * N + c0) = make_float2(d[2], d[3]);
            }
        }
    }
}

// ---------------- rmsnorm: one row per block ----------------
__global__ void rmsnorm_k(const float* __restrict__ x, const float* __restrict__ w,
                          float* __restrict__ out) {
    int row = blockIdx.x;
    int t = threadIdx.x;
    float4 xv = ((const float4*)(x + (size_t)row*DM))[t];
    float s = xv.x*xv.x + xv.y*xv.y + xv.z*xv.z + xv.w*xv.w;
    #pragma unroll
    for (int o = 16; o > 0; o >>= 1) s += __shfl_xor_sync(0xffffffffu, s, o);
    __shared__ float ws[8];
    __shared__ float s_inv;
    if ((t & 31) == 0) ws[t >> 5] = s;
    __syncthreads();
    if (t == 0) {
        float tot = 0.f;
        #pragma unroll
        for (int i = 0; i < 8; i++) tot += ws[i];
        s_inv = rsqrtf(tot / (float)DM + 1e-5f);
    }
    __syncthreads();
    float inv = s_inv;
    float4 wv = ((const float4*)w)[t];
    float4 ov;
    ov.x = xv.x*inv*wv.x; ov.y = xv.y*inv*wv.y;
    ov.z = xv.z*inv*wv.z; ov.w = xv.w*inv*wv.w;
    ((float4*)(out + (size_t)row*DM))[t] = ov;
}

// ---------------- RoPE + head permute ----------------
__global__ void rope_perm_k(const float* __restrict__ lin, const int* __restrict__ pos,
                            float* __restrict__ q, float* __restrict__ k,
                            float* __restrict__ v) {
    int idx = blockIdx.x * blockDim.x + threadIdx.x;
    if (idx >= MT * NH * (DKK/2)) return;
    int i  = idx & 31;
    int hh = (idx >> 5) & (NH-1);
    int t  = idx >> 9;
    int b  = t >> 11;
    int s  = t & (SS - 1);
    size_t src = (size_t)t * DM + hh * DKK + 2*i;
    size_t dst = ((size_t)(b*NH + hh) * SS + s) * DKK + 2*i;
    double ex = -((double)(2*i) / 64.0) * 9.210340371976184;
    float invf = (float)exp(ex);
    float ang = (float)pos[t] * invf;
    float sn, cs;
    sincosf(ang, &sn, &cs);
    float qe = lin[src], qo = lin[src+1];
    q[dst]   = qe*cs - qo*sn;
    q[dst+1] = qe*sn + qo*cs;
    const float* link = lin + (size_t)MT*DM;
    float ke = link[src], ko = link[src+1];
    k[dst]   = ke*cs - ko*sn;
    k[dst+1] = ke*sn + ko*cs;
    const float* linv = lin + (size_t)2*MT*DM;
    v[dst]   = linv[src];
    v[dst+1] = linv[src+1];
}

// ---------------- Flash attention, causal, 64x64 tiles, fp32 ----------------
#define ATT_SMEM (4*64*68*4)
__global__ void __launch_bounds__(256) attn_k(
    const float* __restrict__ Q, const float* __restrict__ Kg,
    const float* __restrict__ Vg, float* __restrict__ O)
{
    extern __shared__ float sm[];
    float* Qt = sm;
    float* Kt = sm + 64*68;
    float* Vs = sm + 2*64*68;
    float* Ps = sm + 3*64*68;
    const int qt = blockIdx.x, h = blockIdx.y, b = blockIdx.z;
    const int tid = threadIdx.x;
    const int tr = tid >> 4;
    const int tc = tid & 15;
    const int q0 = qt * 64;
    const float* Qh = Q  + (size_t)(b*NH + h) * SS * DKK;
    const float* Kh = Kg + (size_t)(b*NH + h) * SS * DKK;
    const float* Vh = Vg + (size_t)(b*NH + h) * SS * DKK;
    const int lr = tid >> 4;
    const int lc = (tid & 15) * 4;

    #pragma unroll
    for (int i = 0; i < 4; i++) {
        int rr = lr + i*16;
        float4 t4 = *(const float4*)(Qh + (size_t)(q0 + rr)*DKK + lc);
        Qt[(lc+0)*68 + rr] = t4.x; Qt[(lc+1)*68 + rr] = t4.y;
        Qt[(lc+2)*68 + rr] = t4.z; Qt[(lc+3)*68 + rr] = t4.w;
    }

    float o[4][4];
    #pragma unroll
    for (int i = 0; i < 4; i++)
        #pragma unroll
        for (int c = 0; c < 4; c++) o[i][c] = 0.f;
    float m[4], l[4];
    #pragma unroll
    for (int i = 0; i < 4; i++) { m[i] = -1e30f; l[i] = 0.f; }

    for (int kt = 0; kt <= qt; kt++) {
        int k0 = kt * 64;
        __syncthreads();
        #pragma unroll
        for (int i = 0; i < 4; i++) {
            int rr = lr + i*16;
            float4 t4 = *(const float4*)(Kh + (size_t)(k0 + rr)*DKK + lc);
            Kt[(lc+0)*68 + rr] = t4.x; Kt[(lc+1)*68 + rr] = t4.y;
            Kt[(lc+2)*68 + rr] = t4.z; Kt[(lc+3)*68 + rr] = t4.w;
            float4 v4 = *(const float4*)(Vh + (size_t)(k0 + rr)*DKK + lc);
            *(float4*)&Vs[rr*68 + lc] = v4;
        }
        __syncthreads();

        float sv[4][4];
        #pragma unroll
        for (int i = 0; i < 4; i++)
            #pragma unroll
            for (int j = 0; j < 4; j++) sv[i][j] = 0.f;
        #pragma unroll 8
        for (int d = 0; d < DKK; d++) {
            float qa[4], kb[4];
            *(float4*)qa = *(const float4*)&Qt[d*68 + tr*4];
            *(float4*)kb = *(const float4*)&Kt[d*68 + tc*4];
            #pragma unroll
            for (int i = 0; i < 4; i++)
                #pragma unroll
                for (int j = 0; j < 4; j++)
                    sv[i][j] = fmaf(qa[i], kb[j], sv[i][j]);
        }

        #pragma unroll
        for (int i = 0; i < 4; i++) {
            int grow = q0 + tr*4 + i;
            #pragma unroll
            for (int j = 0; j < 4; j++) {
                int gcol = k0 + tc*4 + j;
                sv[i][j] = (gcol <= grow) ? sv[i][j] * 0.125f : -1e30f;
            }
        }

        #pragma unroll
        for (int i = 0; i < 4; i++) {
            float rm = fmaxf(fmaxf(sv[i][0], sv[i][1]), fmaxf(sv[i][2], sv[i][3]));
            #pragma unroll
            for (int off = 1; off < 16; off <<= 1)
                rm = fmaxf(rm, __shfl_xor_sync(0xffffffffu, rm, off));
            float mn = fmaxf(m[i], rm);
            float alpha = __expf(m[i] - mn);
            float rs = 0.f;
            #pragma unroll
            for (int j = 0; j < 4; j++) {
                sv[i][j] = __expf(sv[i][j] - mn);
                rs += sv[i][j];
            }
            #pragma unroll
            for (int off = 1; off < 16; off <<= 1)
                rs += __shfl_xor_sync(0xffffffffu, rs, off);
            l[i] = l[i] * alpha + rs;
            m[i] = mn;
            #pragma unroll
            for (int c = 0; c < 4; c++) o[i][c] *= alpha;
            *(float4*)&Ps[(tr*4 + i)*68 + tc*4] =
                make_float4(sv[i][0], sv[i][1], sv[i][2], sv[i][3]);
        }
        __syncthreads();

        #pragma unroll 4
        for (int j = 0; j < 64; j++) {
            float vb[4];
            *(float4*)vb = *(const float4*)&Vs[j*68 + tc*4];
            #pragma unroll
            for (int i = 0; i < 4; i++) {
                float p = Ps[(tr*4 + i)*68 + j];
                #pragma unroll
                for (int c = 0; c < 4; c++)
                    o[i][c] = fmaf(p, vb[c], o[i][c]);
            }
        }
    }

    #pragma unroll
    for (int i = 0; i < 4; i++) {
        float inv = 1.f / l[i];
        int row = q0 + tr*4 + i;
        float4 ov = make_float4(o[i][0]*inv, o[i][1]*inv, o[i][2]*inv, o[i][3]*inv);
        *(float4*)(O + (size_t)(b*SS + row)*DM + h*DKK + tc*4) = ov;
    }
}

// ---------------- silu(a) * g, vectorized ----------------
__global__ void silu_mul_k(float4* __restrict__ a, const float4* __restrict__ g, int n4) {
    int i = blockIdx.x * blockDim.x + threadIdx.x;
    if (i >= n4) return;
    float4 av = a[i], gv = g[i], r;
    r.x = (av.x / (1.f + __expf(-av.x))) * gv.x;
    r.y = (av.y / (1.f + __expf(-av.y))) * gv.y;
    r.z = (av.z / (1.f + __expf(-av.z))) * gv.z;
    r.w = (av.w / (1.f + __expf(-av.w))) * gv.w;
    a[i] = r;
}

// ---------------- launcher ----------------
extern "C" void kernel_launch(void* const* d_in, const int* in_sizes, int n_in,
                              void* d_out, int out_size) {
    const float* x   = (const float*)d_in[0];
    const int*   pos = (const int*)  d_in[1];
    const float* n1w = (const float*)d_in[2];
    const float* n2w = (const float*)d_in[3];
    const float* wq  = (const float*)d_in[4];
    const float* wk  = (const float*)d_in[5];
    const float* wv  = (const float*)d_in[6];
    const float* wo  = (const float*)d_in[7];
    const float* w1  = (const float*)d_in[8];
    const float* w2  = (const float*)d_in[9];
    const float* w3  = (const float*)d_in[10];
    float* out = (float*)d_out;

    float *xn, *lin, *q, *k, *v, *att, *x1, *a, *g;
    cudaGetSymbolAddress((void**)&xn,  g_xn);
    cudaGetSymbolAddress((void**)&lin, g_lin);
    cudaGetSymbolAddress((void**)&q,   g_q);
    cudaGetSymbolAddress((void**)&k,   g_k);
    cudaGetSymbolAddress((void**)&v,   g_v);
    cudaGetSymbolAddress((void**)&att, g_att);
    cudaGetSymbolAddress((void**)&x1,  g_x1);
    cudaGetSymbolAddress((void**)&a,   g_a);
    cudaGetSymbolAddress((void**)&g,   g_g);

    cudaFuncSetAttribute(attn_k, cudaFuncAttributeMaxDynamicSharedMemorySize, ATT_SMEM);
    cudaFuncSetAttribute(gemm_mma, cudaFuncAttributeMaxDynamicSharedMemorySize, GEMM_SMEM);

    // 1) rmsnorm 1
    rmsnorm_k<<<MT, 256>>>(x, n1w, xn);
    // 2) QKV projections (tensor core)
    gemm_mma<<<dim3(DM/128, MT/128), 512, GEMM_SMEM>>>(xn, wq, nullptr, lin,                   MT, DM, DM);
    gemm_mma<<<dim3(DM/128, MT/128), 512, GEMM_SMEM>>>(xn, wk, nullptr, lin + (size_t)MT*DM,   MT, DM, DM);
    gemm_mma<<<dim3(DM/128, MT/128), 512, GEMM_SMEM>>>(xn, wv, nullptr, lin + (size_t)2*MT*DM, MT, DM, DM);
    // 3) rope + permute
    rope_perm_k<<<(MT*NH*(DKK/2))/256, 256>>>(lin, pos, q, k, v);
    // 4) attention
    attn_k<<<dim3(SS/64, NH, BB), 256, ATT_SMEM>>>(q, k, v, att);
    // 5) output projection + residual
    gemm_mma<<<dim3(DM/128, MT/128), 512, GEMM_SMEM>>>(att, wo, x, x1, MT, DM, DM);
    // 6) rmsnorm 2
    rmsnorm_k<<<MT, 256>>>(x1, n2w, xn);
    // 7) FFN up
    gemm_mma<<<dim3(DFF/128, MT/128), 512, GEMM_SMEM>>>(xn, w1, nullptr, a, MT, DFF, DM);
    gemm_mma<<<dim3(DFF/128, MT/128), 512, GEMM_SMEM>>>(xn, w3, nullptr, g, MT, DFF, DM);
    // 8) h = silu(a) * g
    silu_mul_k<<<(MT*DFF/4 + 255)/256, 256>>>((float4*)a, (const float4*)g, MT*DFF/4);
    // 9) down projection + residual -> output
    gemm_mma<<<dim3(DM/128, MT/128), 512, GEMM_SMEM>>>(a, w2, x1, out, MT, DM, DFF);
}